// round 6
// baseline (speedup 1.0000x reference)
#include <cuda_runtime.h>

// FeatureSim: attn[b,i,j] = softmax_j( sum_k w[k]*|x[b,i,k]-x[b,j,k]| ), mask j < len[b].
// B=8, L=1024, F=16 (first 11 used), out f32 [8,1024,1024].
//
// R6: kill the smem e-slab; e lives in registers end-to-end.
//     - TPB=512, 2 key columns per thread (nk: 22 regs), BQ=8 rows per block.
//       e[8][2] floats stay in registers (16 regs) -> no STS / reduce-LDS / norm-LDS.
//     - __launch_bounds__(512,2): 32 warps/SM (8 per SMSP) for latency hiding.
//     - per-row warp butterfly -> red[8][16]; one barrier; 8 warps fold 16 partials
//       to inv[8]; one barrier; register-resident normalize + STG.64.
//     - kept: y = x*|w|*log2e prescale (exp = 1 ex2.approx), sign fold as single
//       LOP3/half, key-mask as -1e30 accumulator bias.

#define L_SEQ 1024
#define FDIM  16
#define NF    11
#define BQ    8             // rows per block
#define TPB   512           // each thread owns 2 consecutive key columns (1 f32x2 pair)
#define BPB   (L_SEQ / BQ)  // 128 blocks per batch

typedef unsigned long long u64;
typedef unsigned int u32;

__device__ __forceinline__ u64 pack2(float lo, float hi) {
    u64 r; asm("mov.b64 %0, {%1, %2};" : "=l"(r) : "f"(lo), "f"(hi)); return r;
}
__device__ __forceinline__ void unpack2(u64 v, float& lo, float& hi) {
    asm("mov.b64 {%0, %1}, %2;" : "=f"(lo), "=f"(hi) : "l"(v));
}
__device__ __forceinline__ u64 add2(u64 a, u64 b) {
    u64 r; asm("add.rn.f32x2 %0, %1, %2;" : "=l"(r) : "l"(a), "l"(b)); return r;
}
__device__ __forceinline__ float ex2(float a) {
    float r; asm("ex2.approx.f32 %0, %1;" : "=f"(r) : "f"(a)); return r;
}
// sgn*|d| per packed half: one LOP3 per 32-bit half: (h & 0x7fffffff) ^ m
__device__ __forceinline__ u64 abssign2(u64 d, u32 m) {
    union { u64 u; uint2 v; } c; c.u = d;
    c.v.x = (c.v.x & 0x7fffffffu) ^ m;
    c.v.y = (c.v.y & 0x7fffffffu) ^ m;
    return c.u;
}

#define LOG2E 1.4426950408889634f

__global__ __launch_bounds__(TPB, 2)
void featsim_kernel(const float* __restrict__ x,
                    const int*   __restrict__ lens,
                    const float* __restrict__ w,
                    float*       __restrict__ out)
{
    const int b    = blockIdx.x / BPB;
    const int rb   = blockIdx.x % BPB;
    const int i0   = rb * BQ;
    const int tid  = threadIdx.x;
    const int lane = tid & 31;
    const int warp = tid >> 5;          // 0..15
    const int j0   = tid * 2;

    __shared__ __align__(16) u64 sq2[BQ][12];   // scaled queries {y,y}; [10] used, [11] pad
    __shared__ float red[BQ][16];               // per-warp row partials
    __shared__ float inv_s[BQ];                 // per-row 1/sum

    // Per-feature: positive scale wl_k = |w_k|*log2e, sign mask m_k (block-uniform).
    u32 m[NF];
    float wl[NF];
#pragma unroll
    for (int k = 0; k < NF; ++k) {
        float wk = w[k];
        m[k]  = __float_as_uint(wk) & 0x80000000u;
        wl[k] = fabsf(wk) * LOG2E;
    }

    // Stage scaled queries: sq2[r][k] = {y, y}, y = x*wl_k.
    if (tid < BQ * NF) {
        int r = tid / NF, k = tid - r * NF;
        float y = x[(size_t)(b * L_SEQ + i0 + r) * FDIM + k] * wl[k];
        sq2[r][k] = pack2(y, y);
    }

    // Keys: 2 cols -> pre-negated scaled pairs nk[k] = {-y(col0), -y(col1)}.
    float kr[2][NF];
#pragma unroll
    for (int cc = 0; cc < 2; ++cc) {
        const float4* kp = reinterpret_cast<const float4*>(
            x + (size_t)(b * L_SEQ + j0 + cc) * FDIM);
        float4 a = kp[0], c = kp[1], d = kp[2];
        kr[cc][0] = a.x;  kr[cc][1] = a.y;  kr[cc][2]  = a.z;  kr[cc][3] = a.w;
        kr[cc][4] = c.x;  kr[cc][5] = c.y;  kr[cc][6]  = c.z;  kr[cc][7] = c.w;
        kr[cc][8] = d.x;  kr[cc][9] = d.y;  kr[cc][10] = d.z;
    }
    u64 nk[NF];
#pragma unroll
    for (int k = 0; k < NF; ++k) {
        float nw = -wl[k];
        nk[k] = pack2(kr[0][k] * nw, kr[1][k] * nw);
    }

    // Key-mask as accumulator bias: invalid col -> -1e30 -> ex2 -> exact 0.
    const int len = lens[b];
    const u64 bias = pack2((j0 + 0 < len) ? 0.f : -1e30f,
                           (j0 + 1 < len) ? 0.f : -1e30f);

    __syncthreads();

    // ---- main loop: e kept in registers for all 8 rows ----
    float e[BQ][2];
#pragma unroll
    for (int r = 0; r < BQ; ++r) {
        const ulonglong2* qp = reinterpret_cast<const ulonglong2*>(sq2[r]);
        u64 s = bias, sb = 0ULL;        // split accumulators (even/odd k)
#pragma unroll
        for (int kk = 0; kk < 5; ++kk) {
            ulonglong2 q = qp[kk];      // LDS.128 broadcast (features 2kk, 2kk+1)
            const int k0 = 2 * kk, k1 = 2 * kk + 1;
            s  = add2(s,  abssign2(add2(q.x, nk[k0]), m[k0]));
            sb = add2(sb, abssign2(add2(q.y, nk[k1]), m[k1]));
        }
        {   // tail feature k=10
            u64 q = sq2[r][10];
            s = add2(s, abssign2(add2(q, nk[10]), m[10]));
        }
        s = add2(s, sb);

        float f0, f1;
        unpack2(s, f0, f1);
        float e0 = ex2(f0), e1 = ex2(f1);
        e[r][0] = e0;
        e[r][1] = e1;

        // per-row warp partial (no consumer in this loop -> overlaps next row's math)
        float ps = e0 + e1;
#pragma unroll
        for (int o = 16; o > 0; o >>= 1)
            ps += __shfl_xor_sync(0xffffffffu, ps, o);
        if (lane == 0) red[r][warp] = ps;
    }
    __syncthreads();

    // ---- fold 16 warp partials per row -> inv_s[row] (warps 0..7, one row each) ----
    if (warp < BQ) {
        float v = (lane < 16) ? red[warp][lane] : 0.f;
#pragma unroll
        for (int o = 8; o > 0; o >>= 1)
            v += __shfl_xor_sync(0xffffffffu, v, o);
        if (lane == 0) {
            float inv; asm("rcp.approx.f32 %0, %1;" : "=f"(inv) : "f"(v));
            inv_s[warp] = inv;          // len>=1 => v>0
        }
    }
    __syncthreads();

    // ---- normalize from registers + store ----
    float2* outb = reinterpret_cast<float2*>(out) + (size_t)(b * L_SEQ + i0) * (L_SEQ / 2);
#pragma unroll
    for (int r = 0; r < BQ; ++r) {
        float inv = inv_s[r];
        outb[(size_t)r * (L_SEQ / 2) + tid] = make_float2(e[r][0] * inv, e[r][1] * inv);
    }
}

extern "C" void kernel_launch(void* const* d_in, const int* in_sizes, int n_in,
                              void* d_out, int out_size)
{
    const float* x    = (const float*)d_in[0];   // [8,1024,16] f32
    const int*   lens = (const int*)d_in[1];     // [8] i32
    const float* w    = (const float*)d_in[2];   // [11] f32
    float*       out  = (float*)d_out;           // [8,1024,1024] f32

    dim3 grid(8 * BPB);   // 1024 blocks
    dim3 block(TPB);
    featsim_kernel<<<grid, block>>>(x, lens, w, out);
}

// round 7
// speedup vs baseline: 1.1676x; 1.1676x over previous
#include <cuda_runtime.h>

// FeatureSim: attn[b,i,j] = softmax_j( sum_k w[k]*|x[b,i,k]-x[b,j,k]| ), mask j < len[b].
// B=8, L=1024, F=16 (first 11 used), out f32 [8,1024,1024].
//
// R7: LSU-pressure attack. L1tex has been the top counter in every round (57%+);
//     kernels are LSU-dispatch bound, not math/occupancy bound (R6 falsified occ theory).
//     - queries stored in smem as PLAIN floats: 3 LDS.128/row deliver 12 q-values
//       (was 6 LDS of pre-duplicated {q,q} delivering 11). {q,q} built on the fly
//       with 1-cycle mov.b64 {r,r} on the slack ALU path. Row-loop LDS halved 48->24.
//     - everything else = R5 (best): C=4 cols/thread, BQ=8, TPB=256, 3 blocks/SM,
//       f32x2 math, single LOP3 abs+sign fold, mask as -1e30 bias, ex2.approx,
//       e-slab + warp-per-row reduction, 3 barriers.

#define L_SEQ 1024
#define FDIM  16
#define NF    11
#define BQ    8             // rows per block
#define TPB   256           // each thread owns 4 consecutive key columns (2 f32x2 pairs)
#define BPB   (L_SEQ / BQ)  // 128 blocks per batch

typedef unsigned long long u64;
typedef unsigned int u32;

__device__ __forceinline__ u64 pack2(float lo, float hi) {
    u64 r; asm("mov.b64 %0, {%1, %2};" : "=l"(r) : "f"(lo), "f"(hi)); return r;
}
// duplicate one float into both halves: single mov.b64 {r,r}
__device__ __forceinline__ u64 dup2(float v) {
    u64 r; asm("mov.b64 %0, {%1, %1};" : "=l"(r) : "f"(v)); return r;
}
__device__ __forceinline__ void unpack2(u64 v, float& lo, float& hi) {
    asm("mov.b64 {%0, %1}, %2;" : "=f"(lo), "=f"(hi) : "l"(v));
}
__device__ __forceinline__ u64 add2(u64 a, u64 b) {
    u64 r; asm("add.rn.f32x2 %0, %1, %2;" : "=l"(r) : "l"(a), "l"(b)); return r;
}
__device__ __forceinline__ float ex2(float a) {
    float r; asm("ex2.approx.f32 %0, %1;" : "=f"(r) : "f"(a)); return r;
}
// sgn*|d| per packed half: one LOP3 per 32-bit half: (h & 0x7fffffff) ^ m
__device__ __forceinline__ u64 abssign2(u64 d, u32 m) {
    union { u64 u; uint2 v; } c; c.u = d;
    c.v.x = (c.v.x & 0x7fffffffu) ^ m;
    c.v.y = (c.v.y & 0x7fffffffu) ^ m;
    return c.u;
}

#define LOG2E 1.4426950408889634f

__global__ __launch_bounds__(TPB, 3)
void featsim_kernel(const float* __restrict__ x,
                    const int*   __restrict__ lens,
                    const float* __restrict__ w,
                    float*       __restrict__ out)
{
    const int b    = blockIdx.x / BPB;
    const int rb   = blockIdx.x % BPB;
    const int i0   = rb * BQ;
    const int tid  = threadIdx.x;
    const int lane = tid & 31;
    const int warp = tid >> 5;
    const int j0   = tid * 4;

    __shared__ __align__(16) float sq[BQ][12];      // scaled queries, PLAIN floats
    __shared__ __align__(16) float se[BQ][L_SEQ];   // unnormalized e staging (32 KB)
    __shared__ float red[BQ];                       // per-row 1/sum

    // Per-feature: positive scale wl_k = |w_k|*log2e, sign mask m_k.
    u32 m[NF];
    float wl[NF];
#pragma unroll
    for (int k = 0; k < NF; ++k) {
        float wk = w[k];
        m[k]  = __float_as_uint(wk) & 0x80000000u;
        wl[k] = fabsf(wk) * LOG2E;
    }

    // Stage scaled queries (plain floats): sq[r][k] = x*wl_k, slot 11 zeroed.
    if (tid < BQ * 12) {
        int r = tid / 12, k = tid - r * 12;
        float y = (k < NF) ? x[(size_t)(b * L_SEQ + i0 + r) * FDIM + k] * wl[k] : 0.f;
        sq[r][k] = y;
    }

    // Keys: 4 cols -> pre-negated scaled pairs.
    float kr[4][NF];
#pragma unroll
    for (int cc = 0; cc < 4; ++cc) {
        const float4* kp = reinterpret_cast<const float4*>(
            x + (size_t)(b * L_SEQ + j0 + cc) * FDIM);
        float4 a = kp[0], c = kp[1], d = kp[2];
        kr[cc][0] = a.x;  kr[cc][1] = a.y;  kr[cc][2]  = a.z;  kr[cc][3] = a.w;
        kr[cc][4] = c.x;  kr[cc][5] = c.y;  kr[cc][6]  = c.z;  kr[cc][7] = c.w;
        kr[cc][8] = d.x;  kr[cc][9] = d.y;  kr[cc][10] = d.z;
    }
    u64 nk0[NF], nk1[NF];
#pragma unroll
    for (int k = 0; k < NF; ++k) {
        float nw = -wl[k];
        nk0[k] = pack2(kr[0][k] * nw, kr[1][k] * nw);
        nk1[k] = pack2(kr[2][k] * nw, kr[3][k] * nw);
    }

    // Key-mask as accumulator bias: invalid col -> -1e30 -> ex2 -> exact 0.
    const int len = lens[b];
    const u64 bias0 = pack2((j0 + 0 < len) ? 0.f : -1e30f,
                            (j0 + 1 < len) ? 0.f : -1e30f);
    const u64 bias1 = pack2((j0 + 2 < len) ? 0.f : -1e30f,
                            (j0 + 3 < len) ? 0.f : -1e30f);

    __syncthreads();

    // ---- main loop: 3 LDS.128 per row; {q,q} built with 1-cyc ALU movs ----
#pragma unroll
    for (int r = 0; r < BQ; ++r) {
        const float4* qp = reinterpret_cast<const float4*>(sq[r]);
        float4 qa = qp[0];              // features 0..3
        float4 qb = qp[1];              // features 4..7
        float4 qc = qp[2];              // features 8..11 (11 unused)
        float qs[NF] = { qa.x, qa.y, qa.z, qa.w,
                         qb.x, qb.y, qb.z, qb.w,
                         qc.x, qc.y, qc.z };

        u64 sa0 = bias0, sb0 = 0ULL;    // split accumulators: even/odd k
        u64 sa1 = bias1, sb1 = 0ULL;
#pragma unroll
        for (int k = 0; k < 10; k += 2) {
            u64 q0 = dup2(qs[k]);
            u64 q1 = dup2(qs[k + 1]);
            sa0 = add2(sa0, abssign2(add2(q0, nk0[k]),     m[k]));
            sa1 = add2(sa1, abssign2(add2(q0, nk1[k]),     m[k]));
            sb0 = add2(sb0, abssign2(add2(q1, nk0[k + 1]), m[k + 1]));
            sb1 = add2(sb1, abssign2(add2(q1, nk1[k + 1]), m[k + 1]));
        }
        {   // tail feature k=10
            u64 q = dup2(qs[10]);
            sa0 = add2(sa0, abssign2(add2(q, nk0[10]), m[10]));
            sa1 = add2(sa1, abssign2(add2(q, nk1[10]), m[10]));
        }
        u64 s0 = add2(sa0, sb0);
        u64 s1 = add2(sa1, sb1);

        float f0, f1, f2, f3;
        unpack2(s0, f0, f1);
        unpack2(s1, f2, f3);
        *reinterpret_cast<float4*>(&se[r][j0]) =
            make_float4(ex2(f0), ex2(f1), ex2(f2), ex2(f3));
    }
    __syncthreads();

    // ---- row sums: warp w reduces row w straight from the e-slab ----
    {
        float acc = 0.f;
#pragma unroll
        for (int p = 0; p < 8; ++p) {
            float4 v = *reinterpret_cast<float4*>(&se[warp][lane * 4 + p * 128]);
            acc += (v.x + v.y) + (v.z + v.w);
        }
#pragma unroll
        for (int o = 16; o > 0; o >>= 1)
            acc += __shfl_xor_sync(0xffffffffu, acc, o);
        if (lane == 0) {
            float inv; asm("rcp.approx.f32 %0, %1;" : "=f"(inv) : "f"(acc));
            red[warp] = inv;                           // len>=1 => acc>0
        }
    }
    __syncthreads();

    // ---- normalize + store ----
    float4* outb = reinterpret_cast<float4*>(out) + (size_t)(b * L_SEQ + i0) * (L_SEQ / 4);
#pragma unroll
    for (int r = 0; r < BQ; ++r) {
        float inv = red[r];
        float4 ev = *reinterpret_cast<float4*>(&se[r][j0]);
        outb[(size_t)r * (L_SEQ / 4) + tid] =
            make_float4(ev.x * inv, ev.y * inv, ev.z * inv, ev.w * inv);
    }
}

extern "C" void kernel_launch(void* const* d_in, const int* in_sizes, int n_in,
                              void* d_out, int out_size)
{
    const float* x    = (const float*)d_in[0];   // [8,1024,16] f32
    const int*   lens = (const int*)d_in[1];     // [8] i32
    const float* w    = (const float*)d_in[2];   // [11] f32
    float*       out  = (float*)d_out;           // [8,1024,1024] f32

    dim3 grid(8 * BPB);   // 1024 blocks
    dim3 block(TPB);
    featsim_kernel<<<grid, block>>>(x, lens, w, out);
}

// round 8
// speedup vs baseline: 1.2728x; 1.0902x over previous
#include <cuda_runtime.h>

// FeatureSim: attn[b,i,j] = softmax_j( sum_k w[k]*|x[b,i,k]-x[b,j,k]| ), mask j < len[b].
// B=8, L=1024, F=16 (first 11 used), out f32 [8,1024,1024].
//
// R8: pure-FFMA core. SASS FADD/FFMA source modifiers make |x| and -x FREE:
//       d   = q_k - kk_c,k          (FADD, negate modifier)
//       s_c = FFMA(|d|, wl_k, s_c)  (abs modifier; wl_k = w_k*log2e, SIGNED)
//     -> 2 fma-pipe ops per (element,feature); zero LOP3, zero dup/pack/unpack movs,
//        zero key prescaling. 4 independent 11-deep FFMA chains for ILP.
//     kept from R5/R7: C=4 cols/thread, BQ=8, TPB=256, 3 blocks/SM pinned,
//     mask as -1e30 accumulator bias, ex2.approx, e-slab + warp-per-row reduce,
//     3 barriers, float4 I/O.

#define L_SEQ 1024
#define FDIM  16
#define NF    11
#define BQ    8             // rows per block
#define TPB   256           // each thread owns 4 consecutive key columns
#define BPB   (L_SEQ / BQ)  // 128 blocks per batch

__device__ __forceinline__ float ex2(float a) {
    float r; asm("ex2.approx.f32 %0, %1;" : "=f"(r) : "f"(a)); return r;
}

#define LOG2E 1.4426950408889634f

__global__ __launch_bounds__(TPB, 3)
void featsim_kernel(const float* __restrict__ x,
                    const int*   __restrict__ lens,
                    const float* __restrict__ w,
                    float*       __restrict__ out)
{
    const int b    = blockIdx.x / BPB;
    const int rb   = blockIdx.x % BPB;
    const int i0   = rb * BQ;
    const int tid  = threadIdx.x;
    const int lane = tid & 31;
    const int warp = tid >> 5;
    const int j0   = tid * 4;

    __shared__ __align__(16) float sq[BQ][12];      // raw queries (11 used, pad 0)
    __shared__ __align__(16) float se[BQ][L_SEQ];   // unnormalized e staging (32 KB)
    __shared__ float red[BQ];                       // per-row 1/sum

    // Signed per-feature scale wl_k = w_k * log2e (sign rides the FFMA multiplier;
    // |d| comes from the free abs source modifier).
    float wl[NF];
#pragma unroll
    for (int k = 0; k < NF; ++k) wl[k] = w[k] * LOG2E;

    // Stage raw queries.
    if (tid < BQ * 12) {
        int r = tid / 12, k = tid - r * 12;
        sq[r][k] = (k < NF) ? x[(size_t)(b * L_SEQ + i0 + r) * FDIM + k] : 0.f;
    }

    // Keys: 4 cols, raw floats straight from LDG (no packing, no prescale).
    float kk[4][NF];
#pragma unroll
    for (int cc = 0; cc < 4; ++cc) {
        const float4* kp = reinterpret_cast<const float4*>(
            x + (size_t)(b * L_SEQ + j0 + cc) * FDIM);
        float4 a = kp[0], c = kp[1], d = kp[2];
        kk[cc][0] = a.x;  kk[cc][1] = a.y;  kk[cc][2]  = a.z;  kk[cc][3] = a.w;
        kk[cc][4] = c.x;  kk[cc][5] = c.y;  kk[cc][6]  = c.z;  kk[cc][7] = c.w;
        kk[cc][8] = d.x;  kk[cc][9] = d.y;  kk[cc][10] = d.z;
    }

    // Key-mask as accumulator bias: invalid col -> -1e30 -> ex2 -> exact 0.
    const int len = lens[b];
    float bias[4];
#pragma unroll
    for (int cc = 0; cc < 4; ++cc) bias[cc] = (j0 + cc < len) ? 0.f : -1e30f;

    __syncthreads();

    // ---- main loop: 3 LDS.128 per row + 88 FADD/FFMA (one pipe, free |.| and -) ----
#pragma unroll
    for (int r = 0; r < BQ; ++r) {
        const float4* qp = reinterpret_cast<const float4*>(sq[r]);
        float4 qa = qp[0];              // features 0..3
        float4 qb = qp[1];              // features 4..7
        float4 qc = qp[2];              // features 8..10 (+pad)
        const float qs[NF] = { qa.x, qa.y, qa.z, qa.w,
                               qb.x, qb.y, qb.z, qb.w,
                               qc.x, qc.y, qc.z };

        float s0 = bias[0], s1 = bias[1], s2 = bias[2], s3 = bias[3];
#pragma unroll
        for (int k = 0; k < NF; ++k) {
            const float q = qs[k], wk = wl[k];
            s0 = fmaf(fabsf(q - kk[0][k]), wk, s0);
            s1 = fmaf(fabsf(q - kk[1][k]), wk, s1);
            s2 = fmaf(fabsf(q - kk[2][k]), wk, s2);
            s3 = fmaf(fabsf(q - kk[3][k]), wk, s3);
        }

        *reinterpret_cast<float4*>(&se[r][j0]) =
            make_float4(ex2(s0), ex2(s1), ex2(s2), ex2(s3));
    }
    __syncthreads();

    // ---- row sums: warp w reduces row w straight from the e-slab ----
    {
        float acc = 0.f;
#pragma unroll
        for (int p = 0; p < 8; ++p) {
            float4 v = *reinterpret_cast<float4*>(&se[warp][lane * 4 + p * 128]);
            acc += (v.x + v.y) + (v.z + v.w);
        }
#pragma unroll
        for (int o = 16; o > 0; o >>= 1)
            acc += __shfl_xor_sync(0xffffffffu, acc, o);
        if (lane == 0) {
            float inv; asm("rcp.approx.f32 %0, %1;" : "=f"(inv) : "f"(acc));
            red[warp] = inv;                           // len>=1 => acc>0
        }
    }
    __syncthreads();

    // ---- normalize + store ----
    float4* outb = reinterpret_cast<float4*>(out) + (size_t)(b * L_SEQ + i0) * (L_SEQ / 4);
#pragma unroll
    for (int r = 0; r < BQ; ++r) {
        float inv = red[r];
        float4 ev = *reinterpret_cast<float4*>(&se[r][j0]);
        outb[(size_t)r * (L_SEQ / 4) + tid] =
            make_float4(ev.x * inv, ev.y * inv, ev.z * inv, ev.w * inv);
    }
}

extern "C" void kernel_launch(void* const* d_in, const int* in_sizes, int n_in,
                              void* d_out, int out_size)
{
    const float* x    = (const float*)d_in[0];   // [8,1024,16] f32
    const int*   lens = (const int*)d_in[1];     // [8] i32
    const float* w    = (const float*)d_in[2];   // [11] f32
    float*       out  = (float*)d_out;           // [8,1024,1024] f32

    dim3 grid(8 * BPB);   // 1024 blocks
    dim3 block(TPB);
    featsim_kernel<<<grid, block>>>(x, lens, w, out);
}